// round 7
// baseline (speedup 1.0000x reference)
#include <cuda_runtime.h>
#include <cuda_fp16.h>
#include <math.h>
#include <stdint.h>

// Problem constants
#define T_TOK   2048
#define KTOP    2
#define NEXP    8
#define HDIM    1024
#define FDIM    4096
#define NASSIGN (T_TOK * KTOP)   // 4096

// Tiling
#define BM 128
#define BN 128
#define BK 32                    // fp16 k per chunk = 2 k16 mma steps
#define NTHREADS 256
#define NSTAGE 3

// Smem row strides (bytes) — conflict-free ldmatrix phases, 16B aligned
#define A_RB 80                  // 32 halfs + 16B pad
#define B_RB 272                 // 128 halfs + 16B pad
#define A_BYTES (BM * A_RB)      // 10240
#define B_BYTES (BK * B_RB)      // 8704
#define STAGE_BYTES (A_BYTES + B_BYTES)
#define SM_ROWSRC (NSTAGE * STAGE_BYTES)          // 56832
#define SMEM_DYN  (SM_ROWSRC + BM * 4 + 128)      // ~57.5 KB

// ---------------------------------------------------------------------------
// Scratch (static device globals — no runtime allocation)
// ---------------------------------------------------------------------------
__device__ __align__(128) int    g_counts[NEXP];
__device__ __align__(128) int    g_offsets[NEXP + 1];
__device__ __align__(128) int    g_cursor[NEXP];
__device__ __align__(128) int    g_row_token[NASSIGN];
__device__ __align__(128) int    g_token_slot[NASSIGN];
__device__ __align__(128) __half g_xh [(size_t)T_TOK * HDIM];        // x fp16
__device__ __align__(128) __half g_w1h[(size_t)NEXP * HDIM * FDIM];  // w1 fp16
__device__ __align__(128) __half g_w2h[(size_t)NEXP * FDIM * HDIM];  // w2 fp16
__device__ __align__(128) __half g_H[(size_t)NASSIGN * FDIM];        // gelu(x@w1)
__device__ __align__(128) float  g_Y[(size_t)NASSIGN * HDIM];        // h@w2

// ---------------------------------------------------------------------------
// PTX helpers
// ---------------------------------------------------------------------------
__device__ __forceinline__ uint32_t cvta_smem(const void* p) {
    uint32_t a;
    asm("{ .reg .u64 t; cvta.to.shared.u64 t, %1; cvt.u32.u64 %0, t; }"
        : "=r"(a) : "l"(p));
    return a;
}
__device__ __forceinline__ void cp_async16(uint32_t saddr, const void* gaddr) {
    asm volatile("cp.async.cg.shared.global [%0], [%1], 16;"
                 :: "r"(saddr), "l"(gaddr) : "memory");
}
#define CP_COMMIT() asm volatile("cp.async.commit_group;" ::: "memory")
#define CP_WAIT(n)  asm volatile("cp.async.wait_group %0;" :: "n"(n) : "memory")

__device__ __forceinline__ void ldsm_x4(uint32_t addr, uint32_t* r) {
    asm volatile("ldmatrix.sync.aligned.m8n8.x4.shared.b16 {%0,%1,%2,%3}, [%4];"
                 : "=r"(r[0]), "=r"(r[1]), "=r"(r[2]), "=r"(r[3]) : "r"(addr));
}
__device__ __forceinline__ void ldsm_x4_t(uint32_t addr, uint32_t* r) {
    asm volatile("ldmatrix.sync.aligned.m8n8.x4.trans.shared.b16 {%0,%1,%2,%3}, [%4];"
                 : "=r"(r[0]), "=r"(r[1]), "=r"(r[2]), "=r"(r[3]) : "r"(addr));
}
__device__ __forceinline__ void mma_f16(float* d, const uint32_t* a, const uint32_t* b) {
    asm volatile(
        "mma.sync.aligned.m16n8k16.row.col.f32.f16.f16.f32 "
        "{%0,%1,%2,%3}, {%4,%5,%6,%7}, {%8,%9}, {%0,%1,%2,%3};\n"
        : "+f"(d[0]), "+f"(d[1]), "+f"(d[2]), "+f"(d[3])
        : "r"(a[0]), "r"(a[1]), "r"(a[2]), "r"(a[3]), "r"(b[0]), "r"(b[1]));
}
__device__ __forceinline__ uint32_t pack_h2(float x, float y) {
    __half2 h = __floats2half2_rn(x, y);
    return *(uint32_t*)&h;
}
__device__ __forceinline__ float gelu_exact(float v) {
    return 0.5f * v * (1.0f + erff(v * 0.70710678118654752f));
}

// ---------------------------------------------------------------------------
// fp32 -> fp16 convert (grid-stride, 8 elems per iteration)
// ---------------------------------------------------------------------------
__global__ void f2h_kernel(const float* __restrict__ src, __half* __restrict__ dst,
                           int n8) {
    for (int i = blockIdx.x * blockDim.x + threadIdx.x; i < n8;
         i += gridDim.x * blockDim.x) {
        const float4* s4 = (const float4*)src + 2 * (size_t)i;
        float4 a = s4[0], b = s4[1];
        uint4 o;
        o.x = pack_h2(a.x, a.y); o.y = pack_h2(a.z, a.w);
        o.z = pack_h2(b.x, b.y); o.w = pack_h2(b.z, b.w);
        ((uint4*)dst)[i] = o;
    }
}

// ---------------------------------------------------------------------------
// Routing with dtype sniffing (int64-declared buffer may actually be int32)
// ---------------------------------------------------------------------------
__global__ void route_kernel(const void* __restrict__ top_experts_raw) {
    const long long* te64 = (const long long*)top_experts_raw;
    const int*       te32 = (const int*)top_experts_raw;
    const int tid = threadIdx.x;

    __shared__ int s_not64;
    if (tid == 0) s_not64 = 0;
    if (tid < NEXP) { g_counts[tid] = 0; g_cursor[tid] = 0; }
    __syncthreads();

    int bad = 0;
    for (int i = tid; i < NASSIGN / 2; i += NTHREADS) {
        long long v = te64[i];
        if (v < 0 || v >= NEXP) bad = 1;
    }
    if (bad) atomicOr(&s_not64, 1);
    __syncthreads();
    const bool is64 = (s_not64 == 0);

    for (int i = tid; i < NASSIGN; i += NTHREADS) {
        int e = is64 ? (int)te64[i] : te32[i];
        atomicAdd(&g_counts[e], 1);
    }
    __syncthreads();
    if (tid == 0) {
        int acc = 0;
        for (int e = 0; e < NEXP; e++) { g_offsets[e] = acc; acc += g_counts[e]; }
        g_offsets[NEXP] = acc;
    }
    __syncthreads();
    for (int i = tid; i < NASSIGN; i += NTHREADS) {
        int e = is64 ? (int)te64[i] : te32[i];
        int pos = g_offsets[e] + atomicAdd(&g_cursor[e], 1);
        g_row_token[pos] = i >> 1;
        g_token_slot[i] = pos;
    }
}

// ---------------------------------------------------------------------------
// Grouped GEMM, fp16: 3-stage cp.async pipeline, ldmatrix, mma m16n8k16.
// Block 128x128, BK=32, 8 warps (2M x 4N, warp 64x32), 1 barrier per chunk.
//   GELU=true : A = g_xh rows gathered via g_row_token -> g_H (fp16)
//   GELU=false: A = g_H rows (contiguous slots)        -> g_Y (fp32)
// ---------------------------------------------------------------------------
template <int KDIM, int NDIM, bool GELU, bool GATHER>
__global__ __launch_bounds__(NTHREADS)
void expert_gemm_h(const __half* __restrict__ A_src, const __half* __restrict__ W) {
    const int e    = blockIdx.z;
    const int base = g_offsets[e];
    const int Me   = g_offsets[e + 1] - base;
    const int m0   = blockIdx.y * BM;
    if (m0 >= Me) return;
    const int n0   = blockIdx.x * BN;

    extern __shared__ __align__(16) unsigned char smem[];
    const uint32_t sb0 = cvta_smem(smem);
    int* rowSrc = (int*)(smem + SM_ROWSRC);

    const int tid = threadIdx.x;
    const int wid = tid >> 5;
    const int lid = tid & 31;

    for (int r = tid; r < BM; r += NTHREADS) {
        int m = m0 + r;
        int safe_m = (m < Me) ? m : 0;
        rowSrc[r] = GATHER ? g_row_token[base + safe_m] : (base + safe_m);
    }
    __syncthreads();

    const __half* __restrict__ Wt = W + (size_t)e * KDIM * NDIM;
    const int NC = KDIM / BK;

    // cp.async coordinates (16B each; 2 A + 2 B per thread per chunk)
    const int a_m0 = (tid + 0 * NTHREADS) >> 2, a_q0 = (tid + 0 * NTHREADS) & 3;
    const int a_m1 = (tid + 1 * NTHREADS) >> 2, a_q1 = (tid + 1 * NTHREADS) & 3;
    const int b_k0 = (tid + 0 * NTHREADS) >> 4, b_c0 = (tid + 0 * NTHREADS) & 15;
    const int b_k1 = (tid + 1 * NTHREADS) >> 4, b_c1 = (tid + 1 * NTHREADS) & 15;

    #define ISSUE(c, stg)                                                           \
        do {                                                                        \
            const int kc0 = (c) * BK;                                               \
            const uint32_t sa = sb0 + (stg) * STAGE_BYTES;                          \
            const uint32_t sbq = sa + A_BYTES;                                      \
            cp_async16(sa + a_m0 * A_RB + a_q0 * 16,                                \
                       A_src + (size_t)rowSrc[a_m0] * KDIM + kc0 + a_q0 * 8);       \
            cp_async16(sa + a_m1 * A_RB + a_q1 * 16,                                \
                       A_src + (size_t)rowSrc[a_m1] * KDIM + kc0 + a_q1 * 8);       \
            cp_async16(sbq + b_k0 * B_RB + b_c0 * 16,                               \
                       Wt + (size_t)(kc0 + b_k0) * NDIM + n0 + b_c0 * 8);           \
            cp_async16(sbq + b_k1 * B_RB + b_c1 * 16,                               \
                       Wt + (size_t)(kc0 + b_k1) * NDIM + n0 + b_c1 * 8);           \
            CP_COMMIT();                                                            \
        } while (0)

    // warp/fragment coordinates
    const int wm  = (wid >> 2) * 64;
    const int wn  = (wid & 3) * 32;
    const int lm8 = lid & 7;
    const int lb1 = (lid >> 3) & 1;
    const int lb2 = lid >> 4;
    const int fr  = lid >> 2;
    const int fc  = lid & 3;

    float acc[4][4][4];
    #pragma unroll
    for (int i = 0; i < 4; i++)
        #pragma unroll
        for (int j = 0; j < 4; j++)
            #pragma unroll
            for (int q = 0; q < 4; q++) acc[i][j][q] = 0.0f;

    // Prologue: 2 chunks in flight
    ISSUE(0, 0);
    if (NC > 1) ISSUE(1, 1);

    int stg = 0;
    for (int c = 0; c < NC; c++) {
        // stage c complete: allow 1 pending group if c+1 was issued, else 0
        if (c + 1 < NC) { CP_WAIT(1); } else { CP_WAIT(0); }
        __syncthreads();   // single barrier: data ready + prev buffers consumed

        const uint32_t sa  = sb0 + stg * STAGE_BYTES;
        const uint32_t sb_ = sa + A_BYTES;

        #pragma unroll
        for (int s = 0; s < 2; s++) {       // two k16 steps per BK=32
            const int k0 = s * 16;
            uint32_t afr[4][4], bfr[4][2];
            #pragma unroll
            for (int i = 0; i < 4; i++) {
                const int row = wm + i * 16 + lm8 + lb1 * 8;
                ldsm_x4(sa + row * A_RB + (k0 + lb2 * 8) * 2, afr[i]);
            }
            #pragma unroll
            for (int j2 = 0; j2 < 2; j2++) {
                const int kk = k0 + lm8 + lb1 * 8;
                const int nn = wn + j2 * 16 + lb2 * 8;
                uint32_t t[4];
                ldsm_x4_t(sb_ + kk * B_RB + nn * 2, t);
                bfr[j2 * 2 + 0][0] = t[0]; bfr[j2 * 2 + 0][1] = t[1];
                bfr[j2 * 2 + 1][0] = t[2]; bfr[j2 * 2 + 1][1] = t[3];
            }
            #pragma unroll
            for (int i = 0; i < 4; i++)
                #pragma unroll
                for (int j = 0; j < 4; j++)
                    mma_f16(acc[i][j], afr[i], bfr[j]);
        }

        // issue chunk c+2 into stage (c+2)%3 — safe: all warps passed the
        // barrier above, so compute(c-1) on that buffer is finished
        if (c + 2 < NC) {
            int nstg = stg + 2; if (nstg >= NSTAGE) nstg -= NSTAGE;
            ISSUE(c + 2, nstg);
        }
        if (++stg == NSTAGE) stg = 0;
    }

    // Epilogue: acc quad -> rows (fr, fr+8), cols (2fc, 2fc+1)
    #pragma unroll
    for (int i = 0; i < 4; i++) {
        const int mrow0 = m0 + wm + i * 16 + fr;
        #pragma unroll
        for (int j = 0; j < 4; j++) {
            const int col = n0 + wn + j * 8 + fc * 2;
            if (GELU) {
                if (mrow0 < Me) {
                    __half2 h = __floats2half2_rn(gelu_exact(acc[i][j][0]),
                                                  gelu_exact(acc[i][j][1]));
                    *(__half2*)(g_H + (size_t)(base + mrow0) * NDIM + col) = h;
                }
                if (mrow0 + 8 < Me) {
                    __half2 h = __floats2half2_rn(gelu_exact(acc[i][j][2]),
                                                  gelu_exact(acc[i][j][3]));
                    *(__half2*)(g_H + (size_t)(base + mrow0 + 8) * NDIM + col) = h;
                }
            } else {
                if (mrow0 < Me) {
                    *(float2*)(g_Y + (size_t)(base + mrow0) * NDIM + col) =
                        make_float2(acc[i][j][0], acc[i][j][1]);
                }
                if (mrow0 + 8 < Me) {
                    *(float2*)(g_Y + (size_t)(base + mrow0 + 8) * NDIM + col) =
                        make_float2(acc[i][j][2], acc[i][j][3]);
                }
            }
        }
    }
    #undef ISSUE
}

// ---------------------------------------------------------------------------
// Combine: out[t] = ew[t,0]*Y[slot(t,0)] + ew[t,1]*Y[slot(t,1)]
// ---------------------------------------------------------------------------
__global__ void combine_kernel(const float* __restrict__ ew, float* __restrict__ out) {
    int idx = blockIdx.x * blockDim.x + threadIdx.x;
    if (idx >= T_TOK * (HDIM / 4)) return;
    int t  = idx / (HDIM / 4);
    int c4 = (idx % (HDIM / 4)) * 4;
    float w0 = ew[t * 2 + 0];
    float w1 = ew[t * 2 + 1];
    int   s0 = g_token_slot[t * 2 + 0];
    int   s1 = g_token_slot[t * 2 + 1];
    float4 y0 = *(const float4*)(g_Y + (size_t)s0 * HDIM + c4);
    float4 y1 = *(const float4*)(g_Y + (size_t)s1 * HDIM + c4);
    float4 o;
    o.x = w0 * y0.x + w1 * y1.x;
    o.y = w0 * y0.y + w1 * y1.y;
    o.z = w0 * y0.z + w1 * y1.z;
    o.w = w0 * y0.w + w1 * y1.w;
    *(float4*)(out + (size_t)t * HDIM + c4) = o;
}

// ---------------------------------------------------------------------------
// kernel_launch: route + converts -> GEMM1 -> GEMM2 -> combine
// ---------------------------------------------------------------------------
extern "C" void kernel_launch(void* const* d_in, const int* in_sizes, int n_in,
                              void* d_out, int out_size) {
    const float* x   = (const float*)d_in[0];
    const float* ew  = (const float*)d_in[2];
    const void*  te  = d_in[3];
    const float* w1  = (const float*)d_in[4];
    const float* w2  = (const float*)d_in[5];
    float*       out = (float*)d_out;

    cudaFuncSetAttribute(expert_gemm_h<HDIM, FDIM, true, true>,
                         cudaFuncAttributeMaxDynamicSharedMemorySize, SMEM_DYN);
    cudaFuncSetAttribute(expert_gemm_h<FDIM, HDIM, false, false>,
                         cudaFuncAttributeMaxDynamicSharedMemorySize, SMEM_DYN);

    route_kernel<<<1, NTHREADS>>>(te);

    __half* xh;  cudaGetSymbolAddress((void**)&xh,  g_xh);
    __half* w1h; cudaGetSymbolAddress((void**)&w1h, g_w1h);
    __half* w2h; cudaGetSymbolAddress((void**)&w2h, g_w2h);
    __half* Hh;  cudaGetSymbolAddress((void**)&Hh,  g_H);

    f2h_kernel<<<1024, NTHREADS>>>(x, xh, (T_TOK * HDIM) / 8);
    f2h_kernel<<<8192, NTHREADS>>>(w1, w1h, (NEXP * HDIM * FDIM) / 8);
    f2h_kernel<<<8192, NTHREADS>>>(w2, w2h, (NEXP * FDIM * HDIM) / 8);

    // GEMM1: gathered xh [Me,H] x w1h[e] [H,F] -> gelu -> g_H (fp16)
    dim3 g1(FDIM / BN, NASSIGN / BM, NEXP);   // 32 x 32 x 8
    expert_gemm_h<HDIM, FDIM, true, true><<<g1, NTHREADS, SMEM_DYN>>>(xh, w1h);

    // GEMM2: g_H [Me,F] x w2h[e] [F,H] -> g_Y (fp32)
    dim3 g2(HDIM / BN, NASSIGN / BM, NEXP);   // 8 x 32 x 8
    expert_gemm_h<FDIM, HDIM, false, false><<<g2, NTHREADS, SMEM_DYN>>>(Hh, w2h);

    // Combine into output
    int total = T_TOK * (HDIM / 4);
    combine_kernel<<<(total + NTHREADS - 1) / NTHREADS, NTHREADS>>>(ew, out);
}

// round 8
// speedup vs baseline: 1.0506x; 1.0506x over previous
#include <cuda_runtime.h>
#include <cuda_fp16.h>
#include <math.h>
#include <stdint.h>

// Problem constants
#define T_TOK   2048
#define KTOP    2
#define NEXP    8
#define HDIM    1024
#define FDIM    4096
#define NASSIGN (T_TOK * KTOP)   // 4096

// Tiling: block 128x256, 8 warps (2M x 4N), warp tile 64x64
#define BM 128
#define BN 256
#define BK 32
#define NTHREADS 256
#define NSTAGE 3

// Smem row strides (bytes) — conflict-free ldmatrix phases, 16B aligned
#define A_RB 80                   // 32 halfs + pad: (5r)%8 distinct
#define B_RB 528                  // 256 halfs + pad: (33k)%8 distinct
#define A_BYTES (BM * A_RB)       // 10240
#define B_BYTES (BK * B_RB)       // 16896
#define STAGE_BYTES (A_BYTES + B_BYTES)          // 27136
#define SM_ROWSRC (NSTAGE * STAGE_BYTES)         // 81408
#define SMEM_DYN  (SM_ROWSRC + BM * 4 + 128)

// ---------------------------------------------------------------------------
// Scratch (static device globals)
// ---------------------------------------------------------------------------
__device__ __align__(128) int    g_counts[NEXP];
__device__ __align__(128) int    g_offsets[NEXP + 1];
__device__ __align__(128) int    g_cursor[NEXP];
__device__ __align__(128) int    g_row_token[NASSIGN];
__device__ __align__(128) int    g_token_slot[NASSIGN];
__device__ __align__(128) __half g_xh [(size_t)T_TOK * HDIM];
__device__ __align__(128) __half g_w1h[(size_t)NEXP * HDIM * FDIM];
__device__ __align__(128) __half g_w2h[(size_t)NEXP * FDIM * HDIM];
__device__ __align__(128) __half g_H[(size_t)NASSIGN * FDIM];
__device__ __align__(128) float  g_Y[(size_t)NASSIGN * HDIM];

// ---------------------------------------------------------------------------
// PTX helpers
// ---------------------------------------------------------------------------
__device__ __forceinline__ uint32_t cvta_smem(const void* p) {
    uint32_t a;
    asm("{ .reg .u64 t; cvta.to.shared.u64 t, %1; cvt.u32.u64 %0, t; }"
        : "=r"(a) : "l"(p));
    return a;
}
__device__ __forceinline__ void cp_async16(uint32_t saddr, const void* gaddr) {
    asm volatile("cp.async.cg.shared.global [%0], [%1], 16;"
                 :: "r"(saddr), "l"(gaddr) : "memory");
}
#define CP_COMMIT() asm volatile("cp.async.commit_group;" ::: "memory")
#define CP_WAIT(n)  asm volatile("cp.async.wait_group %0;" :: "n"(n) : "memory")

__device__ __forceinline__ void ldsm_x4(uint32_t addr, uint32_t* r) {
    asm volatile("ldmatrix.sync.aligned.m8n8.x4.shared.b16 {%0,%1,%2,%3}, [%4];"
                 : "=r"(r[0]), "=r"(r[1]), "=r"(r[2]), "=r"(r[3]) : "r"(addr));
}
__device__ __forceinline__ void ldsm_x4_t(uint32_t addr, uint32_t* r) {
    asm volatile("ldmatrix.sync.aligned.m8n8.x4.trans.shared.b16 {%0,%1,%2,%3}, [%4];"
                 : "=r"(r[0]), "=r"(r[1]), "=r"(r[2]), "=r"(r[3]) : "r"(addr));
}
__device__ __forceinline__ void mma_f16(float* d, const uint32_t* a, const uint32_t* b) {
    asm volatile(
        "mma.sync.aligned.m16n8k16.row.col.f32.f16.f16.f32 "
        "{%0,%1,%2,%3}, {%4,%5,%6,%7}, {%8,%9}, {%0,%1,%2,%3};\n"
        : "+f"(d[0]), "+f"(d[1]), "+f"(d[2]), "+f"(d[3])
        : "r"(a[0]), "r"(a[1]), "r"(a[2]), "r"(a[3]), "r"(b[0]), "r"(b[1]));
}
__device__ __forceinline__ uint32_t pack_h2(float x, float y) {
    __half2 h = __floats2half2_rn(x, y);
    return *(uint32_t*)&h;
}
__device__ __forceinline__ float gelu_exact(float v) {
    return 0.5f * v * (1.0f + erff(v * 0.70710678118654752f));
}

// ---------------------------------------------------------------------------
// fp32 -> fp16 convert
// ---------------------------------------------------------------------------
__global__ void f2h_kernel(const float* __restrict__ src, __half* __restrict__ dst,
                           int n8) {
    for (int i = blockIdx.x * blockDim.x + threadIdx.x; i < n8;
         i += gridDim.x * blockDim.x) {
        const float4* s4 = (const float4*)src + 2 * (size_t)i;
        float4 a = s4[0], b = s4[1];
        uint4 o;
        o.x = pack_h2(a.x, a.y); o.y = pack_h2(a.z, a.w);
        o.z = pack_h2(b.x, b.y); o.w = pack_h2(b.z, b.w);
        ((uint4*)dst)[i] = o;
    }
}

// ---------------------------------------------------------------------------
// Routing with dtype sniffing
// ---------------------------------------------------------------------------
__global__ void route_kernel(const void* __restrict__ top_experts_raw) {
    const long long* te64 = (const long long*)top_experts_raw;
    const int*       te32 = (const int*)top_experts_raw;
    const int tid = threadIdx.x;

    __shared__ int s_not64;
    if (tid == 0) s_not64 = 0;
    if (tid < NEXP) { g_counts[tid] = 0; g_cursor[tid] = 0; }
    __syncthreads();

    int bad = 0;
    for (int i = tid; i < NASSIGN / 2; i += NTHREADS) {
        long long v = te64[i];
        if (v < 0 || v >= NEXP) bad = 1;
    }
    if (bad) atomicOr(&s_not64, 1);
    __syncthreads();
    const bool is64 = (s_not64 == 0);

    for (int i = tid; i < NASSIGN; i += NTHREADS) {
        int e = is64 ? (int)te64[i] : te32[i];
        atomicAdd(&g_counts[e], 1);
    }
    __syncthreads();
    if (tid == 0) {
        int acc = 0;
        for (int e = 0; e < NEXP; e++) { g_offsets[e] = acc; acc += g_counts[e]; }
        g_offsets[NEXP] = acc;
    }
    __syncthreads();
    for (int i = tid; i < NASSIGN; i += NTHREADS) {
        int e = is64 ? (int)te64[i] : te32[i];
        int pos = g_offsets[e] + atomicAdd(&g_cursor[e], 1);
        g_row_token[pos] = i >> 1;
        g_token_slot[i] = pos;
    }
}

// ---------------------------------------------------------------------------
// Grouped GEMM, fp16: block 128x256, warp 64x64, 3-stage cp.async, ldmatrix.
//   GELU=true : A = g_xh rows gathered via g_row_token -> g_H (fp16)
//   GELU=false: A = g_H rows (contiguous slots)        -> g_Y (fp32)
// ---------------------------------------------------------------------------
template <int KDIM, int NDIM, bool GELU, bool GATHER>
__global__ __launch_bounds__(NTHREADS, 1)
void expert_gemm_h(const __half* __restrict__ A_src, const __half* __restrict__ W) {
    const int e    = blockIdx.z;
    const int base = g_offsets[e];
    const int Me   = g_offsets[e + 1] - base;
    const int m0   = blockIdx.y * BM;
    if (m0 >= Me) return;
    const int n0   = blockIdx.x * BN;

    extern __shared__ __align__(16) unsigned char smem[];
    const uint32_t sb0 = cvta_smem(smem);
    int* rowSrc = (int*)(smem + SM_ROWSRC);

    const int tid = threadIdx.x;
    const int wid = tid >> 5;
    const int lid = tid & 31;

    for (int r = tid; r < BM; r += NTHREADS) {
        int m = m0 + r;
        int safe_m = (m < Me) ? m : 0;
        rowSrc[r] = GATHER ? g_row_token[base + safe_m] : (base + safe_m);
    }
    __syncthreads();

    const __half* __restrict__ Wt = W + (size_t)e * KDIM * NDIM;
    const int NC = KDIM / BK;

    // cp.async coords: A 512 16B-chunks (2/thread), B 1024 (4/thread)
    const int a_m0 = (tid + 0 * NTHREADS) >> 2, a_q0 = (tid + 0 * NTHREADS) & 3;
    const int a_m1 = (tid + 1 * NTHREADS) >> 2, a_q1 = (tid + 1 * NTHREADS) & 3;

    #define ISSUE(c, stg)                                                           \
        do {                                                                        \
            const int kc0 = (c) * BK;                                               \
            const uint32_t sa = sb0 + (stg) * STAGE_BYTES;                          \
            const uint32_t sbq = sa + A_BYTES;                                      \
            cp_async16(sa + a_m0 * A_RB + a_q0 * 16,                                \
                       A_src + (size_t)rowSrc[a_m0] * KDIM + kc0 + a_q0 * 8);       \
            cp_async16(sa + a_m1 * A_RB + a_q1 * 16,                                \
                       A_src + (size_t)rowSrc[a_m1] * KDIM + kc0 + a_q1 * 8);       \
            _Pragma("unroll")                                                       \
            for (int jb = 0; jb < 4; jb++) {                                        \
                const int id = jb * NTHREADS + tid;                                 \
                const int kk = id >> 5, cc = id & 31;                               \
                cp_async16(sbq + kk * B_RB + cc * 16,                               \
                           Wt + (size_t)(kc0 + kk) * NDIM + n0 + cc * 8);           \
            }                                                                       \
            CP_COMMIT();                                                            \
        } while (0)

    // warp/fragment coordinates: 2M x 4N warps, warp tile 64x64
    const int wm  = (wid >> 2) * 64;
    const int wn  = (wid & 3) * 64;
    const int lm8 = lid & 7;
    const int lb1 = (lid >> 3) & 1;
    const int lb2 = lid >> 4;
    const int fr  = lid >> 2;
    const int fc  = lid & 3;

    float acc[4][8][4];
    #pragma unroll
    for (int i = 0; i < 4; i++)
        #pragma unroll
        for (int j = 0; j < 8; j++)
            #pragma unroll
            for (int q = 0; q < 4; q++) acc[i][j][q] = 0.0f;

    ISSUE(0, 0);
    if (NC > 1) ISSUE(1, 1);

    int stg = 0;
    for (int c = 0; c < NC; c++) {
        if (c + 1 < NC) { CP_WAIT(1); } else { CP_WAIT(0); }
        __syncthreads();

        const uint32_t sa  = sb0 + stg * STAGE_BYTES;
        const uint32_t sb_ = sa + A_BYTES;

        #pragma unroll
        for (int s = 0; s < 2; s++) {       // two k16 steps per BK=32
            const int k0 = s * 16;
            uint32_t afr[4][4], bfr[8][2];
            #pragma unroll
            for (int i = 0; i < 4; i++) {
                const int row = wm + i * 16 + lm8 + lb1 * 8;
                ldsm_x4(sa + row * A_RB + (k0 + lb2 * 8) * 2, afr[i]);
            }
            #pragma unroll
            for (int j2 = 0; j2 < 4; j2++) {
                const int kk = k0 + lm8 + lb1 * 8;
                const int nn = wn + j2 * 16 + lb2 * 8;
                uint32_t t[4];
                ldsm_x4_t(sb_ + kk * B_RB + nn * 2, t);
                bfr[j2 * 2 + 0][0] = t[0]; bfr[j2 * 2 + 0][1] = t[1];
                bfr[j2 * 2 + 1][0] = t[2]; bfr[j2 * 2 + 1][1] = t[3];
            }
            #pragma unroll
            for (int i = 0; i < 4; i++)
                #pragma unroll
                for (int j = 0; j < 8; j++)
                    mma_f16(acc[i][j], afr[i], bfr[j]);
        }

        if (c + 2 < NC) {
            int nstg = stg + 2; if (nstg >= NSTAGE) nstg -= NSTAGE;
            ISSUE(c + 2, nstg);
        }
        if (++stg == NSTAGE) stg = 0;
    }

    // Epilogue: acc quad -> rows (fr, fr+8), cols (2fc, 2fc+1)
    #pragma unroll
    for (int i = 0; i < 4; i++) {
        const int mrow0 = m0 + wm + i * 16 + fr;
        #pragma unroll
        for (int j = 0; j < 8; j++) {
            const int col = n0 + wn + j * 8 + fc * 2;
            if (GELU) {
                if (mrow0 < Me) {
                    __half2 h = __floats2half2_rn(gelu_exact(acc[i][j][0]),
                                                  gelu_exact(acc[i][j][1]));
                    *(__half2*)(g_H + (size_t)(base + mrow0) * NDIM + col) = h;
                }
                if (mrow0 + 8 < Me) {
                    __half2 h = __floats2half2_rn(gelu_exact(acc[i][j][2]),
                                                  gelu_exact(acc[i][j][3]));
                    *(__half2*)(g_H + (size_t)(base + mrow0 + 8) * NDIM + col) = h;
                }
            } else {
                if (mrow0 < Me) {
                    *(float2*)(g_Y + (size_t)(base + mrow0) * NDIM + col) =
                        make_float2(acc[i][j][0], acc[i][j][1]);
                }
                if (mrow0 + 8 < Me) {
                    *(float2*)(g_Y + (size_t)(base + mrow0 + 8) * NDIM + col) =
                        make_float2(acc[i][j][2], acc[i][j][3]);
                }
            }
        }
    }
    #undef ISSUE
}

// ---------------------------------------------------------------------------
// Combine
// ---------------------------------------------------------------------------
__global__ void combine_kernel(const float* __restrict__ ew, float* __restrict__ out) {
    int idx = blockIdx.x * blockDim.x + threadIdx.x;
    if (idx >= T_TOK * (HDIM / 4)) return;
    int t  = idx / (HDIM / 4);
    int c4 = (idx % (HDIM / 4)) * 4;
    float w0 = ew[t * 2 + 0];
    float w1 = ew[t * 2 + 1];
    int   s0 = g_token_slot[t * 2 + 0];
    int   s1 = g_token_slot[t * 2 + 1];
    float4 y0 = *(const float4*)(g_Y + (size_t)s0 * HDIM + c4);
    float4 y1 = *(const float4*)(g_Y + (size_t)s1 * HDIM + c4);
    float4 o;
    o.x = w0 * y0.x + w1 * y1.x;
    o.y = w0 * y0.y + w1 * y1.y;
    o.z = w0 * y0.z + w1 * y1.z;
    o.w = w0 * y0.w + w1 * y1.w;
    *(float4*)(out + (size_t)t * HDIM + c4) = o;
}

// ---------------------------------------------------------------------------
// kernel_launch
// ---------------------------------------------------------------------------
extern "C" void kernel_launch(void* const* d_in, const int* in_sizes, int n_in,
                              void* d_out, int out_size) {
    const float* x   = (const float*)d_in[0];
    const float* ew  = (const float*)d_in[2];
    const void*  te  = d_in[3];
    const float* w1  = (const float*)d_in[4];
    const float* w2  = (const float*)d_in[5];
    float*       out = (float*)d_out;

    cudaFuncSetAttribute(expert_gemm_h<HDIM, FDIM, true, true>,
                         cudaFuncAttributeMaxDynamicSharedMemorySize, SMEM_DYN);
    cudaFuncSetAttribute(expert_gemm_h<FDIM, HDIM, false, false>,
                         cudaFuncAttributeMaxDynamicSharedMemorySize, SMEM_DYN);

    route_kernel<<<1, NTHREADS>>>(te);

    __half* xh;  cudaGetSymbolAddress((void**)&xh,  g_xh);
    __half* w1h; cudaGetSymbolAddress((void**)&w1h, g_w1h);
    __half* w2h; cudaGetSymbolAddress((void**)&w2h, g_w2h);
    __half* Hh;  cudaGetSymbolAddress((void**)&Hh,  g_H);

    f2h_kernel<<<1024, NTHREADS>>>(x, xh, (T_TOK * HDIM) / 8);
    f2h_kernel<<<8192, NTHREADS>>>(w1, w1h, (NEXP * HDIM * FDIM) / 8);
    f2h_kernel<<<8192, NTHREADS>>>(w2, w2h, (NEXP * FDIM * HDIM) / 8);

    // GEMM1: gathered xh [Me,H] x w1h[e] [H,F] -> gelu -> g_H (fp16)
    dim3 g1(FDIM / BN, NASSIGN / BM, NEXP);   // 16 x 32 x 8
    expert_gemm_h<HDIM, FDIM, true, true><<<g1, NTHREADS, SMEM_DYN>>>(xh, w1h);

    // GEMM2: g_H [Me,F] x w2h[e] [F,H] -> g_Y (fp32)
    dim3 g2(HDIM / BN, NASSIGN / BM, NEXP);   // 4 x 32 x 8
    expert_gemm_h<FDIM, HDIM, false, false><<<g2, NTHREADS, SMEM_DYN>>>(Hh, w2h);

    int total = T_TOK * (HDIM / 4);
    combine_kernel<<<(total + NTHREADS - 1) / NTHREADS, NTHREADS>>>(ew, out);
}